// round 14
// baseline (speedup 1.0000x reference)
#include <cuda_runtime.h>
#include <cuda_fp16.h>
#include <cstdint>
#include <math.h>

#define N_NODES 100000
#define N_EDGES 3200000
#define D_FEAT 64
#define NUM_RELS 20
#define HID_ATTR 32
#define OUT_ATTR 10

#define SCAN_CHUNK 1024
#define SCAN_BLOCKS 98           // ceil(100000/1024)
#define SCAN_PAD (SCAN_BLOCKS * SCAN_CHUNK)

// ---------------- scratch (device globals; no allocation allowed) ----------------
__device__ __half g_T[(size_t)NUM_RELS * N_NODES * D_FEAT];  // 256 MB transformed features (fp16)
__device__ __half g_H1[(size_t)N_NODES * D_FEAT];            // hidden layer output (fp16)
__device__ int    g_cnt[N_NODES];
__device__ int    g_fill[N_NODES];
__device__ int    g_rowptr[N_NODES + 1];
__device__ int    g_scan[SCAN_PAD];
__device__ int    g_bsums[SCAN_BLOCKS];
__device__ int    g_boff[SCAN_BLOCKS];
__device__ int    g_eidx[N_EDGES];                           // sorted-by-dst: etype*N + src
__device__ float  g_sum[D_FEAT];                             // column sums of h2

// ---------------- CSR build kernels (dst-keyed, 100k segments) ----------------
__global__ void k_zero() {
    int i = blockIdx.x * blockDim.x + threadIdx.x;
    if (i < N_NODES) { g_cnt[i] = 0; g_fill[i] = 0; }
    if (blockIdx.x == 0 && threadIdx.x < D_FEAT) g_sum[threadIdx.x] = 0.0f;
}

__global__ void k_count(const int* __restrict__ dst) {
    int e = blockIdx.x * blockDim.x + threadIdx.x;
    if (e < N_EDGES) atomicAdd(&g_cnt[dst[e]], 1);
}

__global__ void k_scan1() {
    __shared__ int sm[256];
    int t = threadIdx.x;
    int base = blockIdx.x * SCAN_CHUNK;
    int v[4];
    int local = 0;
#pragma unroll
    for (int c = 0; c < 4; c++) {
        int idx = base + t * 4 + c;
        v[c] = (idx < N_NODES) ? g_cnt[idx] : 0;
        local += v[c];
    }
    sm[t] = local;
    __syncthreads();
    for (int off = 1; off < 256; off <<= 1) {
        int x = sm[t];
        int y = (t >= off) ? sm[t - off] : 0;
        __syncthreads();
        sm[t] = x + y;
        __syncthreads();
    }
    int run = sm[t] - local;
#pragma unroll
    for (int c = 0; c < 4; c++) {
        run += v[c];
        g_scan[base + t * 4 + c] = run;   // inclusive within chunk
    }
    if (t == 255) g_bsums[blockIdx.x] = sm[255];
}

__global__ void k_scan2() {
    __shared__ int s[128];
    int t = threadIdx.x;
    s[t] = (t < SCAN_BLOCKS) ? g_bsums[t] : 0;
    __syncthreads();
    if (t == 0) {
        int acc = 0;
        for (int i = 0; i < SCAN_BLOCKS; i++) { int x = s[i]; s[i] = acc; acc += x; }
    }
    __syncthreads();
    if (t < SCAN_BLOCKS) g_boff[t] = s[t];
}

__global__ void k_scan3() {
    int i = blockIdx.x * blockDim.x + threadIdx.x;
    if (i < N_NODES) g_rowptr[i + 1] = g_scan[i] + g_boff[i >> 10];
    if (i == 0) g_rowptr[0] = 0;
}

__global__ void k_fill(const int* __restrict__ src, const int* __restrict__ dst,
                       const int* __restrict__ etype) {
    int e = blockIdx.x * blockDim.x + threadIdx.x;
    if (e < N_EDGES) {
        int d = dst[e];
        int pos = g_rowptr[d] + atomicAdd(&g_fill[d], 1);
        g_eidx[pos] = etype[e] * N_NODES + src[e];
    }
}

// T[r, m, :] = X[m, :] @ W[r] for all 20 relations (fp16 mma.sync m16n8k16, fp32 accum).
// CTA = 128 rows x 64 cols, 8 warps; A-frags in registers; W[r+1] register-prefetched.
// IN_HALF: X is fp16 (layer 2 reads H1 without conversion).
#define XS_H_STRIDE 72                      // halves per Xs row
#define XS_HALVES (128 * XS_H_STRIDE)       // 9216 halves = 18432 B
#define WS_H_STRIDE 72                      // halves per Wt row (n-major)
#define WS_HALVES (64 * WS_H_STRIDE)        // 4608 halves = 9216 B
#define MG_SMEM_BYTES ((XS_HALVES + WS_HALVES) * 2)   // 27648 B

template <bool IN_HALF>
__global__ void __launch_bounds__(256) k_mgemm(const void* __restrict__ Xv,
                                               const float* __restrict__ W,
                                               __half* __restrict__ T) {
    extern __shared__ __half smh[];
    __half* Xs = smh;                        // [row][k] halves, stride 72
    __half* Wt = smh + XS_HALVES;            // [n][k] halves, stride 72 (Wt[n][k] = W[k][n])

    const int tid = threadIdx.x;
    const int wid = tid >> 5;
    const int lane = tid & 31;
    const int g = lane >> 2;             // groupID (0..7)
    const int t4 = lane & 3;             // threadID_in_group (0..3)
    const int m0 = blockIdx.x * 128;

    // stage X tile as fp16, zero-padded tail
#pragma unroll
    for (int i = 0; i < 8; i++) {
        int f = i * 256 + tid;           // slot 0..2047 (4 elems each)
        int row = f >> 4;
        int k4 = (f & 15) << 2;
        uint2 u = make_uint2(0u, 0u);
        if (m0 + row < N_NODES) {
            if (IN_HALF) {
                u = *(const uint2*)((const __half*)Xv + (size_t)(m0 + row) * 64 + k4);
            } else {
                float4 v = *(const float4*)((const float*)Xv + (size_t)(m0 + row) * 64 + k4);
                __half2 h0 = __floats2half2_rn(v.x, v.y);
                __half2 h1 = __floats2half2_rn(v.z, v.w);
                u.x = *(uint32_t*)&h0;
                u.y = *(uint32_t*)&h1;
            }
        }
        *(uint2*)(Xs + row * XS_H_STRIDE + k4) = u;
    }
    __syncthreads();

    // hoist A fragments: rows wid*16 + {g, g+8}, 4 k16-steps
    uint32_t a[4][4];
    const int ar0 = wid * 16 + g;
#pragma unroll
    for (int kt = 0; kt < 4; kt++) {
        int kb = kt * 16;
        a[kt][0] = *(const uint32_t*)(Xs + ar0 * XS_H_STRIDE + kb + 2 * t4);
        a[kt][1] = *(const uint32_t*)(Xs + (ar0 + 8) * XS_H_STRIDE + kb + 2 * t4);
        a[kt][2] = *(const uint32_t*)(Xs + ar0 * XS_H_STRIDE + kb + 2 * t4 + 8);
        a[kt][3] = *(const uint32_t*)(Xs + (ar0 + 8) * XS_H_STRIDE + kb + 2 * t4 + 8);
    }

    const int m_lo = m0 + ar0;
    const int m_hi = m_lo + 8;

    // this thread's 8 (n, k-pair) slots of a 64x64 W matrix (same every relation)
    int wn[8], wk[8];
#pragma unroll
    for (int j = 0; j < 8; j++) {
        int p = j * 256 + tid;           // half2 slot 0..2047
        wn[j] = p & 63;                  // n
        wk[j] = (p >> 6) << 1;           // k base (even)
    }

    // prefetch W[0] into registers (16 floats)
    float wreg[16];
#pragma unroll
    for (int j = 0; j < 8; j++) {
        wreg[2 * j]     = W[wk[j] * 64 + wn[j]];
        wreg[2 * j + 1] = W[(wk[j] + 1) * 64 + wn[j]];
    }

    for (int r = 0; r < NUM_RELS; r++) {
        __syncthreads();     // previous relation's Wt reads done; safe to overwrite
#pragma unroll
        for (int j = 0; j < 8; j++) {
            __half2 hw = __floats2half2_rn(wreg[2 * j], wreg[2 * j + 1]);
            *(uint32_t*)(Wt + wn[j] * WS_H_STRIDE + wk[j]) = *(uint32_t*)&hw;
        }
        // issue prefetch of W[r+1]; latency hides under MMA + epilogue below
        if (r + 1 < NUM_RELS) {
            const float* Wn = W + (size_t)(r + 1) * 4096;
#pragma unroll
            for (int j = 0; j < 8; j++) {
                wreg[2 * j]     = Wn[wk[j] * 64 + wn[j]];
                wreg[2 * j + 1] = Wn[(wk[j] + 1) * 64 + wn[j]];
            }
        }
        __syncthreads();

        float c[8][4];
#pragma unroll
        for (int nt = 0; nt < 8; nt++) { c[nt][0] = 0.f; c[nt][1] = 0.f; c[nt][2] = 0.f; c[nt][3] = 0.f; }

#pragma unroll
        for (int kt = 0; kt < 4; kt++) {
            int kb = kt * 16;
            uint32_t b[8][2];
#pragma unroll
            for (int nt = 0; nt < 8; nt++) {
                int n = nt * 8 + g;
                b[nt][0] = *(const uint32_t*)(Wt + n * WS_H_STRIDE + kb + 2 * t4);
                b[nt][1] = *(const uint32_t*)(Wt + n * WS_H_STRIDE + kb + 2 * t4 + 8);
            }
#pragma unroll
            for (int nt = 0; nt < 8; nt++) {
                asm volatile(
                    "mma.sync.aligned.m16n8k16.row.col.f32.f16.f16.f32 "
                    "{%0,%1,%2,%3}, {%4,%5,%6,%7}, {%8,%9}, {%0,%1,%2,%3};"
                    : "+f"(c[nt][0]), "+f"(c[nt][1]), "+f"(c[nt][2]), "+f"(c[nt][3])
                    : "r"(a[kt][0]), "r"(a[kt][1]), "r"(a[kt][2]), "r"(a[kt][3]),
                      "r"(b[nt][0]), "r"(b[nt][1]));
            }
        }

        // epilogue: fp16 stores
        __half* base = T + (size_t)r * N_NODES * 64;
#pragma unroll
        for (int nt = 0; nt < 8; nt++) {
            int col = nt * 8 + t4 * 2;
            if (m_lo < N_NODES)
                *(__half2*)(base + (size_t)m_lo * 64 + col) = __floats2half2_rn(c[nt][0], c[nt][1]);
            if (m_hi < N_NODES)
                *(__half2*)(base + (size_t)m_hi * 64 + col) = __floats2half2_rn(c[nt][2], c[nt][3]);
        }
    }
}

// warp per node: acc = sum_{edges into node} T[eidx(e)][:]  (fp16 rows, fp32 accumulate)
// 8 independent accumulators. HALF_OUT: write fp16 (H1). REDUCE: fold column-sum
// (for graph mean) into the epilogue via shared+global atomics.
template <bool RELU, bool HALF_OUT, bool REDUCE>
__global__ void k_agg(const __half* __restrict__ T, void* __restrict__ outv) {
    __shared__ float sred[D_FEAT];
    int tid = threadIdx.x;
    if (REDUCE) {
        if (tid < D_FEAT) sred[tid] = 0.f;
        __syncthreads();
    }
    int gw = (blockIdx.x * blockDim.x + tid) >> 5;
    int lane = tid & 31;
    float2 acc = make_float2(0.f, 0.f);
    if (gw < N_NODES) {
        int s = g_rowptr[gw];
        int e = g_rowptr[gw + 1];
        float2 a0 = make_float2(0.f, 0.f), a1 = a0, a2 = a0, a3 = a0;
        float2 a4 = a0, a5 = a0, a6 = a0, a7 = a0;
        int i = s;
        for (; i + 7 < e; i += 8) {
            int r0 = g_eidx[i],     r1 = g_eidx[i + 1], r2 = g_eidx[i + 2], r3 = g_eidx[i + 3];
            int r4 = g_eidx[i + 4], r5 = g_eidx[i + 5], r6 = g_eidx[i + 6], r7 = g_eidx[i + 7];
            float2 v0 = __half22float2(*((const __half2*)(T + (size_t)r0 * 64) + lane));
            float2 v1 = __half22float2(*((const __half2*)(T + (size_t)r1 * 64) + lane));
            float2 v2 = __half22float2(*((const __half2*)(T + (size_t)r2 * 64) + lane));
            float2 v3 = __half22float2(*((const __half2*)(T + (size_t)r3 * 64) + lane));
            float2 v4 = __half22float2(*((const __half2*)(T + (size_t)r4 * 64) + lane));
            float2 v5 = __half22float2(*((const __half2*)(T + (size_t)r5 * 64) + lane));
            float2 v6 = __half22float2(*((const __half2*)(T + (size_t)r6 * 64) + lane));
            float2 v7 = __half22float2(*((const __half2*)(T + (size_t)r7 * 64) + lane));
            a0.x += v0.x; a0.y += v0.y;  a1.x += v1.x; a1.y += v1.y;
            a2.x += v2.x; a2.y += v2.y;  a3.x += v3.x; a3.y += v3.y;
            a4.x += v4.x; a4.y += v4.y;  a5.x += v5.x; a5.y += v5.y;
            a6.x += v6.x; a6.y += v6.y;  a7.x += v7.x; a7.y += v7.y;
        }
        for (; i + 3 < e; i += 4) {
            int r0 = g_eidx[i], r1 = g_eidx[i + 1], r2 = g_eidx[i + 2], r3 = g_eidx[i + 3];
            float2 v0 = __half22float2(*((const __half2*)(T + (size_t)r0 * 64) + lane));
            float2 v1 = __half22float2(*((const __half2*)(T + (size_t)r1 * 64) + lane));
            float2 v2 = __half22float2(*((const __half2*)(T + (size_t)r2 * 64) + lane));
            float2 v3 = __half22float2(*((const __half2*)(T + (size_t)r3 * 64) + lane));
            a0.x += v0.x; a0.y += v0.y;  a1.x += v1.x; a1.y += v1.y;
            a2.x += v2.x; a2.y += v2.y;  a3.x += v3.x; a3.y += v3.y;
        }
        for (; i < e; i++) {
            int r0 = g_eidx[i];
            float2 v0 = __half22float2(*((const __half2*)(T + (size_t)r0 * 64) + lane));
            a0.x += v0.x; a0.y += v0.y;
        }
        acc = make_float2(((a0.x + a1.x) + (a2.x + a3.x)) + ((a4.x + a5.x) + (a6.x + a7.x)),
                          ((a0.y + a1.y) + (a2.y + a3.y)) + ((a4.y + a5.y) + (a6.y + a7.y)));
        if (RELU) { acc.x = fmaxf(acc.x, 0.f); acc.y = fmaxf(acc.y, 0.f); }
        if (HALF_OUT) {
            *((__half2*)((__half*)outv + (size_t)gw * 64) + lane) = __floats2half2_rn(acc.x, acc.y);
        } else {
            *((float2*)((float*)outv + (size_t)gw * 64) + lane) = acc;
        }
    }
    if (REDUCE) {
        atomicAdd(&sred[2 * lane], acc.x);
        atomicAdd(&sred[2 * lane + 1], acc.y);
        __syncthreads();
        if (tid < D_FEAT) atomicAdd(&g_sum[tid], sred[tid]);
    }
}

// ---------------- tail: MLP on graph mean ----------------
__global__ void k_mlp(const float* __restrict__ A1w, const float* __restrict__ A1b,
                      const float* __restrict__ A2w, const float* __restrict__ A2b,
                      float* __restrict__ out_a) {
    __shared__ float g[D_FEAT];
    __shared__ float a1[HID_ATTR];
    int t = threadIdx.x;
    if (t < D_FEAT) g[t] = g_sum[t] * (1.0f / (float)N_NODES);
    __syncthreads();
    if (t < HID_ATTR) {
        float s = A1b[t];
#pragma unroll
        for (int k = 0; k < D_FEAT; k++) s += g[k] * A1w[k * HID_ATTR + t];
        a1[t] = fmaxf(s, 0.f);
    }
    __syncthreads();
    if (t < OUT_ATTR) {
        float s = A2b[t];
#pragma unroll
        for (int k = 0; k < HID_ATTR; k++) s += a1[k] * A2w[k * OUT_ATTR + t];
        out_a[t] = 1.0f / (1.0f + expf(-s));
    }
}

// ---------------- launch ----------------
extern "C" void kernel_launch(void* const* d_in, const int* in_sizes, int n_in,
                              void* d_out, int out_size) {
    const float* h     = (const float*)d_in[0];
    const int*   src   = (const int*)d_in[1];
    const int*   dst   = (const int*)d_in[2];
    const int*   etype = (const int*)d_in[3];
    const float* W1    = (const float*)d_in[4];
    const float* W2    = (const float*)d_in[5];
    const float* A1w   = (const float*)d_in[6];
    const float* A1b   = (const float*)d_in[7];
    const float* A2w   = (const float*)d_in[8];
    const float* A2b   = (const float*)d_in[9];
    float* out = (float*)d_out;

    __half* T;   cudaGetSymbolAddress((void**)&T,  g_T);
    __half* H1;  cudaGetSymbolAddress((void**)&H1, g_H1);

    cudaFuncSetAttribute(k_mgemm<false>, cudaFuncAttributeMaxDynamicSharedMemorySize, MG_SMEM_BYTES);
    cudaFuncSetAttribute(k_mgemm<true>,  cudaFuncAttributeMaxDynamicSharedMemorySize, MG_SMEM_BYTES);

    // side stream + events for CSR || mgemm1 overlap (created once; graph-capture
    // records fork/join as parallel branches). No device allocation involved.
    static cudaStream_t s_side = nullptr;
    static cudaEvent_t  ev_fork = nullptr, ev_csr = nullptr;
    if (s_side == nullptr) {
        cudaStreamCreateWithFlags(&s_side, cudaStreamNonBlocking);
        cudaEventCreateWithFlags(&ev_fork, cudaEventDisableTiming);
        cudaEventCreateWithFlags(&ev_csr, cudaEventDisableTiming);
    }

    const int EB = (N_EDGES + 255) / 256;          // 12500
    const int NB = (N_NODES + 255) / 256;          // 391
    const int GEMM_BLOCKS = (N_NODES + 127) / 128;       // 782
    const int AGG_BLOCKS = (N_NODES * 32 + 255) / 256;   // 12500, warp per node

    // fork: CSR build on side stream, concurrent with layer-1 transform
    cudaEventRecord(ev_fork, 0);
    cudaStreamWaitEvent(s_side, ev_fork, 0);

    k_zero<<<NB, 256, 0, s_side>>>();
    k_count<<<EB, 256, 0, s_side>>>(dst);
    k_scan1<<<SCAN_BLOCKS, 256, 0, s_side>>>();
    k_scan2<<<1, 128, 0, s_side>>>();
    k_scan3<<<NB, 256, 0, s_side>>>();
    k_fill<<<EB, 256, 0, s_side>>>(src, dst, etype);
    cudaEventRecord(ev_csr, s_side);

    // layer 1 transform on main stream (independent of CSR)
    k_mgemm<false><<<GEMM_BLOCKS, 256, MG_SMEM_BYTES>>>(h, W1, T);

    // join: aggregation needs both CSR and T
    cudaStreamWaitEvent(0, ev_csr, 0);
    k_agg<true, true, false><<<AGG_BLOCKS, 256>>>(T, H1);

    // layer 2: transform + aggregate (no activation; fused column-sum reduce)
    k_mgemm<true><<<GEMM_BLOCKS, 256, MG_SMEM_BYTES>>>(H1, W2, T);
    k_agg<false, false, true><<<AGG_BLOCKS, 256>>>(T, out);

    // attributor MLP on graph mean -> last 10 floats of d_out
    k_mlp<<<1, 64>>>(A1w, A1b, A2w, A2b, out + (size_t)N_NODES * D_FEAT);
}

// round 17
// speedup vs baseline: 1.0367x; 1.0367x over previous
#include <cuda_runtime.h>
#include <cuda_fp16.h>
#include <cstdint>
#include <math.h>

#define N_NODES 100000
#define N_EDGES 3200000
#define D_FEAT 64
#define NUM_RELS 20
#define HID_ATTR 32
#define OUT_ATTR 10

#define SCAN_CHUNK 1024
#define SCAN_BLOCKS 98           // ceil(100000/1024)
#define SCAN_PAD (SCAN_BLOCKS * SCAN_CHUNK)

// ---------------- scratch (device globals; no allocation allowed) ----------------
__device__ __half g_T[(size_t)NUM_RELS * N_NODES * D_FEAT];  // 256 MB transformed features (fp16)
__device__ __half g_H1[(size_t)N_NODES * D_FEAT];            // hidden layer output (fp16)
__device__ int    g_cnt[N_NODES];
__device__ int    g_fill[N_NODES];
__device__ int    g_rowptr[N_NODES + 1];
__device__ int    g_scan[SCAN_PAD];
__device__ int    g_bsums[SCAN_BLOCKS];
__device__ int    g_boff[SCAN_BLOCKS];
__device__ int    g_eidx[N_EDGES];                           // sorted-by-dst: etype*N + src
__device__ float  g_sum[D_FEAT];                             // column sums of h2

// ---------------- CSR build kernels (dst-keyed, 100k segments) ----------------
__global__ void k_zero() {
    int i = blockIdx.x * blockDim.x + threadIdx.x;
    if (i < N_NODES) { g_cnt[i] = 0; g_fill[i] = 0; }
    if (blockIdx.x == 0 && threadIdx.x < D_FEAT) g_sum[threadIdx.x] = 0.0f;
}

__global__ void k_count(const int* __restrict__ dst) {
    int e = blockIdx.x * blockDim.x + threadIdx.x;
    if (e < N_EDGES) atomicAdd(&g_cnt[dst[e]], 1);
}

__global__ void k_scan1() {
    __shared__ int sm[256];
    int t = threadIdx.x;
    int base = blockIdx.x * SCAN_CHUNK;
    int v[4];
    int local = 0;
#pragma unroll
    for (int c = 0; c < 4; c++) {
        int idx = base + t * 4 + c;
        v[c] = (idx < N_NODES) ? g_cnt[idx] : 0;
        local += v[c];
    }
    sm[t] = local;
    __syncthreads();
    for (int off = 1; off < 256; off <<= 1) {
        int x = sm[t];
        int y = (t >= off) ? sm[t - off] : 0;
        __syncthreads();
        sm[t] = x + y;
        __syncthreads();
    }
    int run = sm[t] - local;
#pragma unroll
    for (int c = 0; c < 4; c++) {
        run += v[c];
        g_scan[base + t * 4 + c] = run;   // inclusive within chunk
    }
    if (t == 255) g_bsums[blockIdx.x] = sm[255];
}

__global__ void k_scan2() {
    __shared__ int s[128];
    int t = threadIdx.x;
    s[t] = (t < SCAN_BLOCKS) ? g_bsums[t] : 0;
    __syncthreads();
    if (t == 0) {
        int acc = 0;
        for (int i = 0; i < SCAN_BLOCKS; i++) { int x = s[i]; s[i] = acc; acc += x; }
    }
    __syncthreads();
    if (t < SCAN_BLOCKS) g_boff[t] = s[t];
}

__global__ void k_scan3() {
    int i = blockIdx.x * blockDim.x + threadIdx.x;
    if (i < N_NODES) g_rowptr[i + 1] = g_scan[i] + g_boff[i >> 10];
    if (i == 0) g_rowptr[0] = 0;
}

__global__ void k_fill(const int* __restrict__ src, const int* __restrict__ dst,
                       const int* __restrict__ etype) {
    int e = blockIdx.x * blockDim.x + threadIdx.x;
    if (e < N_EDGES) {
        int d = dst[e];
        int pos = g_rowptr[d] + atomicAdd(&g_fill[d], 1);
        g_eidx[pos] = etype[e] * N_NODES + src[e];
    }
}

// T[r, m, :] = X[m, :] @ W[r] for all 20 relations (fp16 mma.sync m16n8k16, fp32 accum).
// CTA = 128 rows x 64 cols, 8 warps; A-frags in registers; W[r+1] register-prefetched.
// IN_HALF: X is fp16 (layer 2 reads H1 without conversion).
#define XS_H_STRIDE 72                      // halves per Xs row
#define XS_HALVES (128 * XS_H_STRIDE)       // 9216 halves = 18432 B
#define WS_H_STRIDE 72                      // halves per Wt row (n-major)
#define WS_HALVES (64 * WS_H_STRIDE)        // 4608 halves = 9216 B
#define MG_SMEM_BYTES ((XS_HALVES + WS_HALVES) * 2)   // 27648 B

template <bool IN_HALF>
__global__ void __launch_bounds__(256) k_mgemm(const void* __restrict__ Xv,
                                               const float* __restrict__ W,
                                               __half* __restrict__ T) {
    extern __shared__ __half smh[];
    __half* Xs = smh;                        // [row][k] halves, stride 72
    __half* Wt = smh + XS_HALVES;            // [n][k] halves, stride 72 (Wt[n][k] = W[k][n])

    const int tid = threadIdx.x;
    const int wid = tid >> 5;
    const int lane = tid & 31;
    const int g = lane >> 2;             // groupID (0..7)
    const int t4 = lane & 3;             // threadID_in_group (0..3)
    const int m0 = blockIdx.x * 128;

    // stage X tile as fp16, zero-padded tail
#pragma unroll
    for (int i = 0; i < 8; i++) {
        int f = i * 256 + tid;           // slot 0..2047 (4 elems each)
        int row = f >> 4;
        int k4 = (f & 15) << 2;
        uint2 u = make_uint2(0u, 0u);
        if (m0 + row < N_NODES) {
            if (IN_HALF) {
                u = *(const uint2*)((const __half*)Xv + (size_t)(m0 + row) * 64 + k4);
            } else {
                float4 v = *(const float4*)((const float*)Xv + (size_t)(m0 + row) * 64 + k4);
                __half2 h0 = __floats2half2_rn(v.x, v.y);
                __half2 h1 = __floats2half2_rn(v.z, v.w);
                u.x = *(uint32_t*)&h0;
                u.y = *(uint32_t*)&h1;
            }
        }
        *(uint2*)(Xs + row * XS_H_STRIDE + k4) = u;
    }
    __syncthreads();

    // hoist A fragments: rows wid*16 + {g, g+8}, 4 k16-steps
    uint32_t a[4][4];
    const int ar0 = wid * 16 + g;
#pragma unroll
    for (int kt = 0; kt < 4; kt++) {
        int kb = kt * 16;
        a[kt][0] = *(const uint32_t*)(Xs + ar0 * XS_H_STRIDE + kb + 2 * t4);
        a[kt][1] = *(const uint32_t*)(Xs + (ar0 + 8) * XS_H_STRIDE + kb + 2 * t4);
        a[kt][2] = *(const uint32_t*)(Xs + ar0 * XS_H_STRIDE + kb + 2 * t4 + 8);
        a[kt][3] = *(const uint32_t*)(Xs + (ar0 + 8) * XS_H_STRIDE + kb + 2 * t4 + 8);
    }

    const int m_lo = m0 + ar0;
    const int m_hi = m_lo + 8;

    // this thread's 8 (n, k-pair) slots of a 64x64 W matrix (same every relation)
    int wn[8], wk[8];
#pragma unroll
    for (int j = 0; j < 8; j++) {
        int p = j * 256 + tid;           // half2 slot 0..2047
        wn[j] = p & 63;                  // n
        wk[j] = (p >> 6) << 1;           // k base (even)
    }

    // prefetch W[0] into registers (16 floats)
    float wreg[16];
#pragma unroll
    for (int j = 0; j < 8; j++) {
        wreg[2 * j]     = W[wk[j] * 64 + wn[j]];
        wreg[2 * j + 1] = W[(wk[j] + 1) * 64 + wn[j]];
    }

    for (int r = 0; r < NUM_RELS; r++) {
        __syncthreads();     // previous relation's Wt reads done; safe to overwrite
#pragma unroll
        for (int j = 0; j < 8; j++) {
            __half2 hw = __floats2half2_rn(wreg[2 * j], wreg[2 * j + 1]);
            *(uint32_t*)(Wt + wn[j] * WS_H_STRIDE + wk[j]) = *(uint32_t*)&hw;
        }
        // issue prefetch of W[r+1]; latency hides under MMA + epilogue below
        if (r + 1 < NUM_RELS) {
            const float* Wn = W + (size_t)(r + 1) * 4096;
#pragma unroll
            for (int j = 0; j < 8; j++) {
                wreg[2 * j]     = Wn[wk[j] * 64 + wn[j]];
                wreg[2 * j + 1] = Wn[(wk[j] + 1) * 64 + wn[j]];
            }
        }
        __syncthreads();

        float c[8][4];
#pragma unroll
        for (int nt = 0; nt < 8; nt++) { c[nt][0] = 0.f; c[nt][1] = 0.f; c[nt][2] = 0.f; c[nt][3] = 0.f; }

#pragma unroll
        for (int kt = 0; kt < 4; kt++) {
            int kb = kt * 16;
            uint32_t b[8][2];
#pragma unroll
            for (int nt = 0; nt < 8; nt++) {
                int n = nt * 8 + g;
                b[nt][0] = *(const uint32_t*)(Wt + n * WS_H_STRIDE + kb + 2 * t4);
                b[nt][1] = *(const uint32_t*)(Wt + n * WS_H_STRIDE + kb + 2 * t4 + 8);
            }
#pragma unroll
            for (int nt = 0; nt < 8; nt++) {
                asm volatile(
                    "mma.sync.aligned.m16n8k16.row.col.f32.f16.f16.f32 "
                    "{%0,%1,%2,%3}, {%4,%5,%6,%7}, {%8,%9}, {%0,%1,%2,%3};"
                    : "+f"(c[nt][0]), "+f"(c[nt][1]), "+f"(c[nt][2]), "+f"(c[nt][3])
                    : "r"(a[kt][0]), "r"(a[kt][1]), "r"(a[kt][2]), "r"(a[kt][3]),
                      "r"(b[nt][0]), "r"(b[nt][1]));
            }
        }

        // epilogue: fp16 stores
        __half* base = T + (size_t)r * N_NODES * 64;
#pragma unroll
        for (int nt = 0; nt < 8; nt++) {
            int col = nt * 8 + t4 * 2;
            if (m_lo < N_NODES)
                *(__half2*)(base + (size_t)m_lo * 64 + col) = __floats2half2_rn(c[nt][0], c[nt][1]);
            if (m_hi < N_NODES)
                *(__half2*)(base + (size_t)m_hi * 64 + col) = __floats2half2_rn(c[nt][2], c[nt][3]);
        }
    }
}

// warp per node: acc = sum_{edges into node} T[eidx(e)][:]  (fp16 rows, fp32 accumulate)
// 4 independent accumulators (R12 champion loop). HALF_OUT: write fp16 (H1).
template <bool RELU, bool HALF_OUT>
__global__ void k_agg(const __half* __restrict__ T, void* __restrict__ outv) {
    int gw = (blockIdx.x * blockDim.x + threadIdx.x) >> 5;
    int lane = threadIdx.x & 31;
    if (gw >= N_NODES) return;
    int s = g_rowptr[gw];
    int e = g_rowptr[gw + 1];
    float2 acc0 = make_float2(0.f, 0.f);
    float2 acc1 = make_float2(0.f, 0.f);
    float2 acc2 = make_float2(0.f, 0.f);
    float2 acc3 = make_float2(0.f, 0.f);
    int i = s;
    for (; i + 3 < e; i += 4) {
        int r0 = g_eidx[i];
        int r1 = g_eidx[i + 1];
        int r2 = g_eidx[i + 2];
        int r3 = g_eidx[i + 3];
        float2 v0 = __half22float2(*((const __half2*)(T + (size_t)r0 * 64) + lane));
        float2 v1 = __half22float2(*((const __half2*)(T + (size_t)r1 * 64) + lane));
        float2 v2 = __half22float2(*((const __half2*)(T + (size_t)r2 * 64) + lane));
        float2 v3 = __half22float2(*((const __half2*)(T + (size_t)r3 * 64) + lane));
        acc0.x += v0.x; acc0.y += v0.y;
        acc1.x += v1.x; acc1.y += v1.y;
        acc2.x += v2.x; acc2.y += v2.y;
        acc3.x += v3.x; acc3.y += v3.y;
    }
    for (; i < e; i++) {
        int r0 = g_eidx[i];
        float2 v0 = __half22float2(*((const __half2*)(T + (size_t)r0 * 64) + lane));
        acc0.x += v0.x; acc0.y += v0.y;
    }
    float2 acc = make_float2((acc0.x + acc1.x) + (acc2.x + acc3.x),
                             (acc0.y + acc1.y) + (acc2.y + acc3.y));
    if (RELU) { acc.x = fmaxf(acc.x, 0.f); acc.y = fmaxf(acc.y, 0.f); }
    if (HALF_OUT) {
        *((__half2*)((__half*)outv + (size_t)gw * 64) + lane) = __floats2half2_rn(acc.x, acc.y);
    } else {
        *((float2*)((float*)outv + (size_t)gw * 64) + lane) = acc;
    }
}

// ---------------- tail: graph mean + MLP ----------------
__global__ void k_reduce(const float* __restrict__ h2) {
    __shared__ float sm[D_FEAT];
    int t = threadIdx.x;
    if (t < D_FEAT) sm[t] = 0.f;
    __syncthreads();
    float acc = 0.f;
    const long total = (long)N_NODES * D_FEAT;
    for (long i = (long)blockIdx.x * blockDim.x + t; i < total; i += (long)gridDim.x * blockDim.x)
        acc += h2[i];
    atomicAdd(&sm[t & 63], acc);
    __syncthreads();
    if (t < D_FEAT) atomicAdd(&g_sum[t], sm[t]);
}

__global__ void k_mlp(const float* __restrict__ A1w, const float* __restrict__ A1b,
                      const float* __restrict__ A2w, const float* __restrict__ A2b,
                      float* __restrict__ out_a) {
    __shared__ float g[D_FEAT];
    __shared__ float a1[HID_ATTR];
    int t = threadIdx.x;
    if (t < D_FEAT) g[t] = g_sum[t] * (1.0f / (float)N_NODES);
    __syncthreads();
    if (t < HID_ATTR) {
        float s = A1b[t];
#pragma unroll
        for (int k = 0; k < D_FEAT; k++) s += g[k] * A1w[k * HID_ATTR + t];
        a1[t] = fmaxf(s, 0.f);
    }
    __syncthreads();
    if (t < OUT_ATTR) {
        float s = A2b[t];
#pragma unroll
        for (int k = 0; k < HID_ATTR; k++) s += a1[k] * A2w[k * OUT_ATTR + t];
        out_a[t] = 1.0f / (1.0f + expf(-s));
    }
}

// ---------------- launch ----------------
extern "C" void kernel_launch(void* const* d_in, const int* in_sizes, int n_in,
                              void* d_out, int out_size) {
    const float* h     = (const float*)d_in[0];
    const int*   src   = (const int*)d_in[1];
    const int*   dst   = (const int*)d_in[2];
    const int*   etype = (const int*)d_in[3];
    const float* W1    = (const float*)d_in[4];
    const float* W2    = (const float*)d_in[5];
    const float* A1w   = (const float*)d_in[6];
    const float* A1b   = (const float*)d_in[7];
    const float* A2w   = (const float*)d_in[8];
    const float* A2b   = (const float*)d_in[9];
    float* out = (float*)d_out;

    __half* T;   cudaGetSymbolAddress((void**)&T,  g_T);
    __half* H1;  cudaGetSymbolAddress((void**)&H1, g_H1);

    cudaFuncSetAttribute(k_mgemm<false>, cudaFuncAttributeMaxDynamicSharedMemorySize, MG_SMEM_BYTES);
    cudaFuncSetAttribute(k_mgemm<true>,  cudaFuncAttributeMaxDynamicSharedMemorySize, MG_SMEM_BYTES);

    // side stream + events for CSR || mgemm1 overlap (created once; graph-capture
    // records fork/join as parallel branches). No device allocation involved.
    static cudaStream_t s_side = nullptr;
    static cudaEvent_t  ev_fork = nullptr, ev_csr = nullptr;
    if (s_side == nullptr) {
        cudaStreamCreateWithFlags(&s_side, cudaStreamNonBlocking);
        cudaEventCreateWithFlags(&ev_fork, cudaEventDisableTiming);
        cudaEventCreateWithFlags(&ev_csr, cudaEventDisableTiming);
    }

    const int EB = (N_EDGES + 255) / 256;          // 12500
    const int NB = (N_NODES + 255) / 256;          // 391
    const int GEMM_BLOCKS = (N_NODES + 127) / 128;       // 782
    const int AGG_BLOCKS = (N_NODES * 32 + 255) / 256;   // 12500, warp per node

    // fork: CSR build on side stream, concurrent with layer-1 transform
    cudaEventRecord(ev_fork, 0);
    cudaStreamWaitEvent(s_side, ev_fork, 0);

    k_zero<<<NB, 256, 0, s_side>>>();
    k_count<<<EB, 256, 0, s_side>>>(dst);
    k_scan1<<<SCAN_BLOCKS, 256, 0, s_side>>>();
    k_scan2<<<1, 128, 0, s_side>>>();
    k_scan3<<<NB, 256, 0, s_side>>>();
    k_fill<<<EB, 256, 0, s_side>>>(src, dst, etype);
    cudaEventRecord(ev_csr, s_side);

    // layer 1 transform on main stream (independent of CSR)
    k_mgemm<false><<<GEMM_BLOCKS, 256, MG_SMEM_BYTES>>>(h, W1, T);

    // join: aggregation needs both CSR and T
    cudaStreamWaitEvent(0, ev_csr, 0);
    k_agg<true, true><<<AGG_BLOCKS, 256>>>(T, H1);

    // layer 2: transform + aggregate (no activation) -> h2 straight into d_out
    k_mgemm<true><<<GEMM_BLOCKS, 256, MG_SMEM_BYTES>>>(H1, W2, T);
    k_agg<false, false><<<AGG_BLOCKS, 256>>>(T, out);

    // graph mean + attributor MLP -> last 10 floats of d_out
    k_reduce<<<256, 256>>>(out);
    k_mlp<<<1, 64>>>(A1w, A1b, A2w, A2b, out + (size_t)N_NODES * D_FEAT);
}